// round 10
// baseline (speedup 1.0000x reference)
#include <cuda_runtime.h>
#include <cuda_bf16.h>
#include <cstdint>

#define MAX_B 8192
#define MAX_WARPS 8192
__device__ int   g_S[MAX_B + 1];        // exclusive prefix of valid chunks/row
__device__ int   g_W;                   // total valid chunks
__device__ float g_warp_sum[MAX_WARPS]; // per-warp weighted partial sums
__device__ int   g_done_ctr = 0;

// ---------------------------------------------------------------------------
// Kernel A: exclusive prefix scan of V[i] = ceil(L[i]/4) over B rows.
// One CTA, 1024 threads, 4 rows per thread. Deterministic.
// ---------------------------------------------------------------------------
__global__ void scan_kernel(const int* __restrict__ lens, int B) {
    const int tid = threadIdx.x;
    int v[4];
    int tsum = 0;
    #pragma unroll
    for (int j = 0; j < 4; j++) {
        int r = tid * 4 + j;
        int L = (r < B) ? lens[r] : 0;
        v[j] = (L + 3) >> 2;
        tsum += v[j];
    }

    // Block exclusive scan of 1024 thread sums.
    __shared__ int s_warp[32];
    int x = tsum;
    #pragma unroll
    for (int off = 1; off < 32; off <<= 1) {
        int y = __shfl_up_sync(0xFFFFFFFFu, x, off);
        if ((tid & 31) >= off) x += y;
    }
    if ((tid & 31) == 31) s_warp[tid >> 5] = x;
    __syncthreads();
    if (tid < 32) {
        int y = s_warp[tid];
        #pragma unroll
        for (int off = 1; off < 32; off <<= 1) {
            int z = __shfl_up_sync(0xFFFFFFFFu, y, off);
            if (tid >= off) y += z;
        }
        s_warp[tid] = y;
    }
    __syncthreads();
    int excl = x - tsum + ((tid >= 32) ? s_warp[(tid >> 5) - 1] : 0);

    #pragma unroll
    for (int j = 0; j < 4; j++) {
        int r = tid * 4 + j;
        if (r < B) g_S[r] = excl;
        excl += v[j];
    }
    if (tid == blockDim.x - 1) {
        g_S[B] = excl;
        g_W = excl;
    }
}

// ---------------------------------------------------------------------------
// Kernel B: perfectly balanced streaming. Warp w owns global valid-chunk
// range [w*W/nw, (w+1)*W/nw): equal load counts for every warp -> no
// stragglers, full sustained occupancy. Binary search in g_S locates the
// starting row; segments are contiguous & coalesced.
//   loss = (1/B) * sum_row (1/L) * sum_{t<L} (pred - log(align))^2
// Deterministic: assignment is a pure function of (w, W); fixed accumulation
// and reduce order.
// ---------------------------------------------------------------------------
template <int BLOCK>
__global__ void __launch_bounds__(BLOCK)
dploss_balanced_kernel(const float* __restrict__ pred,
                       const float* __restrict__ align,
                       const int* __restrict__ lens,
                       float* __restrict__ out,
                       int C, int B, int nWarps) {
    const int lane = threadIdx.x & 31;
    const int w = (blockIdx.x * BLOCK + threadIdx.x) >> 5;

    const int W = g_W;
    const long long startLL = (long long)w * W / nWarps;
    const long long endLL   = (long long)(w + 1) * W / nWarps;
    int remaining = (int)(endLL - startLL);
    const int start = (int)startLL;

    float acc = 0.0f;

    if (remaining > 0) {
        // Binary search: largest r with g_S[r] <= start.
        int lo = 0, hi = B;
        while (lo + 1 < hi) {
            int mid = (lo + hi) >> 1;
            if (g_S[mid] <= start) lo = mid; else hi = mid;
        }
        int r = lo;
        int c = start - g_S[r];            // valid-chunk offset within row r

        while (remaining > 0) {
            const int L = __ldg(lens + r);
            const int nfull = L >> 2;
            const int V = (L + 3) >> 2;
            const int take = min(V - c, remaining);
            const int segEnd = c + take;
            const float rcpL = __frcp_rn((float)L);
            const size_t base = (size_t)r * (size_t)C;
            const float4* __restrict__ p4 = reinterpret_cast<const float4*>(pred) + base;
            const float4* __restrict__ a4 = reinterpret_cast<const float4*>(align) + base;

            const int fullEnd = min(segEnd, nfull);
            float s0 = 0.0f, s1 = 0.0f, s2 = 0.0f, s3 = 0.0f;

            int cc = c + lane;
            // Hot loop: 4 full chunks / iter, 8 independent LDG.128.
            for (; cc + 96 < fullEnd; cc += 128) {
                float4 pA = p4[cc];
                float4 aA = a4[cc];
                float4 pB = p4[cc + 32];
                float4 aB = a4[cc + 32];
                float4 pC = p4[cc + 64];
                float4 aC = a4[cc + 64];
                float4 pD = p4[cc + 96];
                float4 aD = a4[cc + 96];
                float d;
                d = pA.x - __logf(aA.x); s0 = fmaf(d, d, s0);
                d = pA.y - __logf(aA.y); s0 = fmaf(d, d, s0);
                d = pA.z - __logf(aA.z); s0 = fmaf(d, d, s0);
                d = pA.w - __logf(aA.w); s0 = fmaf(d, d, s0);
                d = pB.x - __logf(aB.x); s1 = fmaf(d, d, s1);
                d = pB.y - __logf(aB.y); s1 = fmaf(d, d, s1);
                d = pB.z - __logf(aB.z); s1 = fmaf(d, d, s1);
                d = pB.w - __logf(aB.w); s1 = fmaf(d, d, s1);
                d = pC.x - __logf(aC.x); s2 = fmaf(d, d, s2);
                d = pC.y - __logf(aC.y); s2 = fmaf(d, d, s2);
                d = pC.z - __logf(aC.z); s2 = fmaf(d, d, s2);
                d = pC.w - __logf(aC.w); s2 = fmaf(d, d, s2);
                d = pD.x - __logf(aD.x); s3 = fmaf(d, d, s3);
                d = pD.y - __logf(aD.y); s3 = fmaf(d, d, s3);
                d = pD.z - __logf(aD.z); s3 = fmaf(d, d, s3);
                d = pD.w - __logf(aD.w); s3 = fmaf(d, d, s3);
            }
            for (; cc < fullEnd; cc += 32) {
                float4 p = p4[cc];
                float4 a = a4[cc];
                float d;
                d = p.x - __logf(a.x); s0 = fmaf(d, d, s0);
                d = p.y - __logf(a.y); s1 = fmaf(d, d, s1);
                d = p.z - __logf(a.z); s2 = fmaf(d, d, s2);
                d = p.w - __logf(a.w); s3 = fmaf(d, d, s3);
            }
            // Partial tail chunk (index nfull, 1..3 valid) if inside segment.
            // Safe read: L&3 != 0 implies L < T, so chunk nfull < C.
            if ((L & 3) && segEnd > nfull && lane == (nfull & 31)) {
                float4 p = p4[nfull];
                float4 a = a4[nfull];
                int rem = L & 3;
                float d;
                d = p.x - __logf(a.x); s0 = fmaf(d, d, s0);
                if (rem > 1) { d = p.y - __logf(a.y); s1 = fmaf(d, d, s1); }
                if (rem > 2) { d = p.z - __logf(a.z); s2 = fmaf(d, d, s2); }
            }

            acc = fmaf((s0 + s1) + (s2 + s3), rcpL, acc);
            remaining -= take;
            r++;
            c = 0;
        }
    }

    // Warp reduction (fixed order) -> per-warp slot.
    #pragma unroll
    for (int off = 16; off > 0; off >>= 1)
        acc += __shfl_down_sync(0xFFFFFFFFu, acc, off);
    if (lane == 0)
        g_warp_sum[w] = acc;

    // Last CTA reduces all warp sums in fixed order.
    __syncthreads();
    __shared__ bool s_is_last;
    if (threadIdx.x == 0) {
        __threadfence();
        int old = atomicAdd(&g_done_ctr, 1);
        s_is_last = (old == (int)gridDim.x - 1);
    }
    __syncthreads();

    if (s_is_last) {
        float v = 0.0f;
        for (int i = threadIdx.x; i < nWarps; i += BLOCK)
            v += g_warp_sum[i];
        __shared__ float s_fin[BLOCK / 32];
        #pragma unroll
        for (int off = 16; off > 0; off >>= 1)
            v += __shfl_down_sync(0xFFFFFFFFu, v, off);
        if ((threadIdx.x & 31) == 0) s_fin[threadIdx.x >> 5] = v;
        __syncthreads();
        if (threadIdx.x == 0) {
            float t = 0.0f;
            #pragma unroll
            for (int k = 0; k < BLOCK / 32; k++) t += s_fin[k];
            out[0] = t / (float)B;
            g_done_ctr = 0;            // reset for next graph replay
        }
    }
}

extern "C" void kernel_launch(void* const* d_in, const int* in_sizes, int n_in,
                              void* d_out, int out_size) {
    const float* pred  = (const float*)d_in[0];
    const float* align = (const float*)d_in[1];
    const int*   lens  = (const int*)d_in[2];
    float* out = (float*)d_out;

    const int B = in_sizes[2];
    const int T = in_sizes[0] / B;
    const int C = T >> 2;

    scan_kernel<<<1, 1024>>>(lens, B);

    constexpr int BLOCK = 128;
    int grid = 1024;                       // one resident wave (<=1184 @64regs)
    int nWarps = grid * (BLOCK / 32);
    if (nWarps > MAX_WARPS) { grid = MAX_WARPS / (BLOCK / 32); nWarps = grid * (BLOCK / 32); }

    dploss_balanced_kernel<BLOCK><<<grid, BLOCK>>>(pred, align, lens, out,
                                                   C, B, nWarps);
}